// round 17
// baseline (speedup 1.0000x reference)
#include <cuda_runtime.h>
#include <cuda_fp16.h>
#include <cstdint>
#include <cstddef>

// B=16, N=2048, D=64, fp32. Output = concat(out [B,N,D], attn [B,N,N]).
#define B_ 16
#define N_ 2048
#define D_ 64
#define MT 64
#define KT 128
#define NTILE (N_ / KT)

// smem: sZ[64] | Q fp16 64x64 (8KB) | K fp16 128x64 x2 | V fp16 128x64 x2
#define OFF_SZ 0
#define OFF_Q  1024
#define OFF_K0 (OFF_Q + 8192)            // 9216
#define KBUF   16384
#define OFF_V0 (OFF_K0 + 2 * KBUF)       // 41984
#define SMEM_BYTES (OFF_V0 + 2 * KBUF)   // 74752 (~73KB) -> 2 CTAs/SM

__device__ __forceinline__ float fex2(float x) {
    float r; asm("ex2.approx.f32 %0, %1;" : "=f"(r) : "f"(x)); return r;
}
__device__ __forceinline__ uint32_t smem_u32(const void* p) {
    uint32_t a; asm("{ .reg .u64 t; cvta.to.shared.u64 t, %1; cvt.u32.u64 %0, t; }"
                    : "=r"(a) : "l"(p)); return a;
}
// pack (lo=a, hi=b) as fp16x2
__device__ __forceinline__ uint32_t packh2(float a, float b) {
    uint32_t r; asm("cvt.rn.f16x2.f32 %0, %1, %2;" : "=r"(r) : "f"(b), "f"(a)); return r;
}
__device__ __forceinline__ void ldmx4(uint32_t* r, uint32_t a) {
    asm volatile("ldmatrix.sync.aligned.m8n8.x4.shared.b16 {%0,%1,%2,%3}, [%4];"
        : "=r"(r[0]), "=r"(r[1]), "=r"(r[2]), "=r"(r[3]) : "r"(a));
}
__device__ __forceinline__ void ldmx4t(uint32_t* r, uint32_t a) {
    asm volatile("ldmatrix.sync.aligned.m8n8.x4.trans.shared.b16 {%0,%1,%2,%3}, [%4];"
        : "=r"(r[0]), "=r"(r[1]), "=r"(r[2]), "=r"(r[3]) : "r"(a));
}
// D += A*B, m16n8k16 fp16 inputs, fp32 accumulate.
__device__ __forceinline__ void mma16(float* c, const uint32_t* a, uint32_t b0, uint32_t b1) {
    asm volatile(
        "mma.sync.aligned.m16n8k16.row.col.f32.f16.f16.f32 "
        "{%0,%1,%2,%3}, {%4,%5,%6,%7}, {%8,%9}, {%0,%1,%2,%3};\n"
        : "+f"(c[0]), "+f"(c[1]), "+f"(c[2]), "+f"(c[3])
        : "r"(a[0]), "r"(a[1]), "r"(a[2]), "r"(a[3]), "r"(b0), "r"(b1));
}

// [ROWS x 64] fp32 tile (row stride 64) -> fp16 smem, 128B rows, XOR swizzle
// byte = r*128 + (cbyte ^ ((r&7)*16)) so ldmatrix 8-row reads are conflict-free.
template <int ROWS>
__device__ __forceinline__ void fill_tile(char* __restrict__ sbase,
                                          const float* __restrict__ g, int tid) {
#pragma unroll
    for (int i = 0; i < ROWS / 16; i++) {
        int idx = tid + i * 256;                 // float4 index
        int r = idx >> 4, c4 = idx & 15;
        float4 v = *(const float4*)(g + (size_t)r * D_ + c4 * 4);
        uint32_t h01 = packh2(v.x, v.y);
        uint32_t h23 = packh2(v.z, v.w);
        uint32_t byte = (uint32_t)(r * 128 + ((c4 * 8) ^ ((r & 7) * 16)));
        *(uint2*)(sbase + byte) = make_uint2(h01, h23);
    }
}

__global__ void __launch_bounds__(256, 2)
attn_kernel(const float* __restrict__ Q, const float* __restrict__ K,
            const float* __restrict__ V,
            float* __restrict__ out, float* __restrict__ attn,
            int has_out, int has_attn) {
    extern __shared__ char smem[];
    const uint32_t sb = smem_u32(smem);
    float* sZ = (float*)(smem + OFF_SZ);

    const int tid  = threadIdx.x;
    const int lane = tid & 31;
    const int wid  = tid >> 5;
    const int g  = lane >> 2;             // 0..7
    const int qd = lane & 3;              // 0..3
    const int wm = wid >> 1;              // 0..3 -> 16-row slice
    const int wn = wid & 1;               // 0..1 -> 64-key slice
    const int b  = blockIdx.x >> 5;
    const int m0 = (blockIdx.x & 31) * MT;
    const float CEXP = 0.18033688011112042f;   // log2(e)/sqrt(64)

    const float* Kg = K + (size_t)b * N_ * D_;
    const float* Vg = V + (size_t)b * N_ * D_;

    // ldmatrix per-thread address components
    const int lr = lane & 15;                       // row within 16-row footprint
    const int lh = (lane >> 4) * 16;                // 16B half select
    const uint32_t xorv = (uint32_t)((lr & 7) * 16);

    if (tid < MT) sZ[tid] = 0.0f;
    fill_tile<MT>(smem + OFF_Q, Q + ((size_t)b * N_ + m0) * D_, tid);

    // Precomputed ldmatrix row-base addresses (buffer 0; add sel for buffer 1)
    const uint32_t qA = sb + OFF_Q + (uint32_t)((wm * 16 + lr) * 128);
    uint32_t kB[4];
#pragma unroll
    for (int nb = 0; nb < 4; nb++)
        kB[nb] = sb + OFF_K0 + (uint32_t)((wn * 64 + nb * 16 + lr) * 128);
    const uint32_t vB = sb + OFF_V0 + (uint32_t)((wn * 64 + lr) * 128);

    float oacc[8][4];                     // 16 rows x 64 dims (partial over warp's keys)
#pragma unroll
    for (int ni = 0; ni < 8; ni++)
#pragma unroll
        for (int x = 0; x < 4; x++) oacc[ni][x] = 0.0f;
    float zp[2] = {0.f, 0.f};

    // ---------------- Pass 1: Z + partial out = exp(S) @ V ----------------
    // Double-buffered: body j = { fill(j+1) || QK(j) -> exp -> AV(j) ; sync }
    fill_tile<KT>(smem + OFF_K0, Kg, tid);
    fill_tile<KT>(smem + OFF_V0, Vg, tid);
    __syncthreads();

    for (int j = 0; j < NTILE; j++) {
        if (j + 1 < NTILE) {
            uint32_t fsel = (uint32_t)(((j + 1) & 1) * KBUF);
            fill_tile<KT>(smem + OFF_K0 + fsel, Kg + (size_t)(j + 1) * KT * D_, tid);
            fill_tile<KT>(smem + OFF_V0 + fsel, Vg + (size_t)(j + 1) * KT * D_, tid);
        }
        const uint32_t sel = (uint32_t)((j & 1) * KBUF);

        // ---- QK: S[16x64] per warp, 4 k16-steps over D=64 ----
        float sacc[8][4];
#pragma unroll
        for (int ni = 0; ni < 8; ni++)
#pragma unroll
            for (int x = 0; x < 4; x++) sacc[ni][x] = 0.0f;
#pragma unroll
        for (int ks = 0; ks < 4; ks++) {
            const uint32_t koff = (uint32_t)((ks * 32 + lh) ^ xorv);
            uint32_t a0[4];
            ldmx4(a0, qA + koff);
#pragma unroll
            for (int nb = 0; nb < 4; nb++) {
                uint32_t bv[4];
                ldmx4(bv, kB[nb] + sel + koff);
                mma16(sacc[2 * nb],     a0, bv[0], bv[2]);
                mma16(sacc[2 * nb + 1], a0, bv[1], bv[3]);
            }
        }

        // ---- exp + pack: C-frag becomes fp16 A-frag directly ----
        uint32_t W[8][2];
#pragma unroll
        for (int ni = 0; ni < 8; ni++) {
            float e0 = fex2(sacc[ni][0] * CEXP);
            float e1 = fex2(sacc[ni][1] * CEXP);
            float e2 = fex2(sacc[ni][2] * CEXP);
            float e3 = fex2(sacc[ni][3] * CEXP);
            zp[0] += e0 + e1;
            zp[1] += e2 + e3;
            W[ni][0] = packh2(e0, e1);   // (row g,   keys 2qd,2qd+1)
            W[ni][1] = packh2(e2, e3);   // (row g+8, keys 2qd,2qd+1)
        }

        // ---- AV: oacc += W @ V, 4 k16-steps over warp's 64 keys ----
#pragma unroll
        for (int ks = 0; ks < 4; ks++) {
            uint32_t a0[4] = {W[2 * ks][0], W[2 * ks][1],
                              W[2 * ks + 1][0], W[2 * ks + 1][1]};
            const uint32_t vrow = vB + sel + (uint32_t)(ks * 2048);   // +16 key rows
#pragma unroll
            for (int nb = 0; nb < 4; nb++) {
                uint32_t bv[4];
                ldmx4t(bv, vrow + (uint32_t)(((nb * 32 + lh)) ^ xorv));
                mma16(oacc[2 * nb],     a0, bv[0], bv[1]);
                mma16(oacc[2 * nb + 1], a0, bv[2], bv[3]);
            }
        }
        __syncthreads();
    }

    // ---------------- Z reduction ----------------
#pragma unroll
    for (int h = 0; h < 2; h++) {
        float v = zp[h];
        v += __shfl_xor_sync(0xffffffffu, v, 1);
        v += __shfl_xor_sync(0xffffffffu, v, 2);
        if (qd == 0) atomicAdd(&sZ[wm * 16 + h * 8 + g], v);
    }
    __syncthreads();
    if (tid < MT) sZ[tid] = 1.0f / sZ[tid];
    __syncthreads();

    // ---------- out: reduce wn partials through smem, scale, write ----------
    if (has_out) {
        float* Ob = (float*)(smem + OFF_K0);   // [64][64] scratch (16KB, buffer K0)
        if (wn == 1) {
            int r0 = wm * 16 + g;
#pragma unroll
            for (int ni = 0; ni < 8; ni++) {
                int c = ni * 8 + 2 * qd;
                Ob[r0 * 64 + c]           = oacc[ni][0];
                Ob[r0 * 64 + c + 1]       = oacc[ni][1];
                Ob[(r0 + 8) * 64 + c]     = oacc[ni][2];
                Ob[(r0 + 8) * 64 + c + 1] = oacc[ni][3];
            }
        }
        __syncthreads();
        if (wn == 0) {
            float* ob = out + ((size_t)b * N_ + m0) * D_;
            int r0 = wm * 16 + g;
            float z0 = sZ[r0], z1 = sZ[r0 + 8];
#pragma unroll
            for (int ni = 0; ni < 8; ni++) {
                int c = ni * 8 + 2 * qd;
                float o0 = (oacc[ni][0] + Ob[r0 * 64 + c]) * z0;
                float o1 = (oacc[ni][1] + Ob[r0 * 64 + c + 1]) * z0;
                float o2 = (oacc[ni][2] + Ob[(r0 + 8) * 64 + c]) * z1;
                float o3 = (oacc[ni][3] + Ob[(r0 + 8) * 64 + c + 1]) * z1;
                *(float2*)(ob + (size_t)r0 * D_ + c)       = make_float2(o0, o1);
                *(float2*)(ob + (size_t)(r0 + 8) * D_ + c) = make_float2(o2, o3);
            }
        }
        __syncthreads();   // scratch consumed before pass 2 refills K0
    }

    // -------- Pass 2: recompute S, write normalized weights (K double-buffered) --------
    if (has_attn) {
        const float zi0 = sZ[wm * 16 + g];
        const float zi1 = sZ[wm * 16 + 8 + g];
        float* ab = attn + ((size_t)b * N_ + m0) * (size_t)N_;

        fill_tile<KT>(smem + OFF_K0, Kg, tid);
        __syncthreads();

        for (int j = 0; j < NTILE; j++) {
            if (j + 1 < NTILE) {
                uint32_t fsel = (uint32_t)(((j + 1) & 1) * KBUF);
                fill_tile<KT>(smem + OFF_K0 + fsel, Kg + (size_t)(j + 1) * KT * D_, tid);
            }
            const uint32_t sel = (uint32_t)((j & 1) * KBUF);

            float sacc[8][4];
#pragma unroll
            for (int ni = 0; ni < 8; ni++)
#pragma unroll
                for (int x = 0; x < 4; x++) sacc[ni][x] = 0.0f;
#pragma unroll
            for (int ks = 0; ks < 4; ks++) {
                const uint32_t koff = (uint32_t)((ks * 32 + lh) ^ xorv);
                uint32_t a0[4];
                ldmx4(a0, qA + koff);
#pragma unroll
                for (int nb = 0; nb < 4; nb++) {
                    uint32_t bv[4];
                    ldmx4(bv, kB[nb] + sel + koff);
                    mma16(sacc[2 * nb],     a0, bv[0], bv[2]);
                    mma16(sacc[2 * nb + 1], a0, bv[1], bv[3]);
                }
            }

            int r0 = wm * 16 + g;
#pragma unroll
            for (int ni = 0; ni < 8; ni++) {
                int c = j * KT + wn * 64 + ni * 8 + 2 * qd;
                float e0 = fex2(sacc[ni][0] * CEXP) * zi0;
                float e1 = fex2(sacc[ni][1] * CEXP) * zi0;
                float e2 = fex2(sacc[ni][2] * CEXP) * zi1;
                float e3 = fex2(sacc[ni][3] * CEXP) * zi1;
                *(float2*)(ab + (size_t)r0 * N_ + c)       = make_float2(e0, e1);
                *(float2*)(ab + (size_t)(r0 + 8) * N_ + c) = make_float2(e2, e3);
            }
            __syncthreads();
        }
    }
}

extern "C" void kernel_launch(void* const* d_in, const int* in_sizes, int n_in,
                              void* d_out, int out_size) {
    (void)in_sizes; (void)n_in;
    const float* Q = (const float*)d_in[0];
    const float* K = (const float*)d_in[1];
    const float* V = (const float*)d_in[2];
    float* o = (float*)d_out;

    const long long OUT_E  = (long long)B_ * N_ * D_;   //  2,097,152
    const long long ATTN_E = (long long)B_ * N_ * N_;   // 67,108,864

    int has_out = 1, has_attn = 1;
    float* attnp = o + OUT_E;
    if ((long long)out_size == OUT_E)       { has_attn = 0; attnp = o; }
    else if ((long long)out_size == ATTN_E) { has_out  = 0; attnp = o; }

    cudaFuncSetAttribute(attn_kernel,
                         cudaFuncAttributeMaxDynamicSharedMemorySize, SMEM_BYTES);
    attn_kernel<<<B_ * (N_ / MT), 256, SMEM_BYTES>>>(Q, K, V, o, attnp,
                                                     has_out, has_attn);
}